// round 13
// baseline (speedup 1.0000x reference)
#include <cuda_runtime.h>
#include <cuda_fp16.h>
#include <math.h>
#include <stdint.h>

// ----------------------------------------------------------------------------
// Problem constants
// ----------------------------------------------------------------------------
#define NB 4
#define LM 1024
#define LS 1024
#define NE 768
#define NH 12
#define HD 64
#define HALF 512
#define NTOK (NB * LM)          // 4096
#define FCD (4 * NE)            // 3072
#define LN_EPS 1e-5f
#define FULLMASK 0xffffffffu

// ----------------------------------------------------------------------------
// Scratch (device globals -- no runtime allocation allowed)
// ----------------------------------------------------------------------------
__device__ float  g_x1[NTOK * NE];
__device__ __half g_qh [NTOK * NE];   // Q/K/V in fp16
__device__ __half g_kh [NTOK * NE];
__device__ __half g_vh [NTOK * NE];
__device__ __half g_xnh[NTOK * NE];   // LN outputs (fp16)
__device__ __half g_snh[NTOK * NE];
__device__ __half g_yh [NTOK * NE];   // attention out (fp16)
__device__ __half g_hh [NTOK * FCD]; // GELU activations (fp16)
__device__ __half g_wq [NE * NE];     // weights (fp16)
__device__ __half g_wk [NE * NE];
__device__ __half g_wv [NE * NE];
__device__ __half g_wc [NE * NE];
__device__ __half g_wfc[FCD * NE];
__device__ __half g_wpr[NE * FCD];
__device__ int g_src[NB * LS];

__device__ __forceinline__ uint32_t smem_u32(const void* p) {
    return (uint32_t)__cvta_generic_to_shared(p);
}

// ----------------------------------------------------------------------------
// Batched fp32 -> fp16 conversion: 6 segments in one launch.
// ----------------------------------------------------------------------------
__global__ void f2h6_kernel(const float* __restrict__ s0, const float* __restrict__ s1,
                            const float* __restrict__ s2, const float* __restrict__ s3,
                            const float* __restrict__ s4, const float* __restrict__ s5,
                            __half* __restrict__ d0, __half* __restrict__ d1,
                            __half* __restrict__ d2, __half* __restrict__ d3,
                            __half* __restrict__ d4, __half* __restrict__ d5,
                            int n_sq, int n_fc)
{
    const float* in; __half* out; int n;
    switch (blockIdx.y) {
        case 0: in = s0; out = d0; n = n_sq; break;
        case 1: in = s1; out = d1; n = n_sq; break;
        case 2: in = s2; out = d2; n = n_sq; break;
        case 3: in = s3; out = d3; n = n_sq; break;
        case 4: in = s4; out = d4; n = n_fc; break;
        default: in = s5; out = d5; n = n_fc; break;
    }
    int i = (blockIdx.x * 256 + threadIdx.x) * 8;
    if (i < n) {
        float4 a = *(const float4*)(in + i);
        float4 b = *(const float4*)(in + i + 4);
        __half2 h[4];
        h[0] = __floats2half2_rn(a.x, a.y);
        h[1] = __floats2half2_rn(a.z, a.w);
        h[2] = __floats2half2_rn(b.x, b.y);
        h[3] = __floats2half2_rn(b.z, b.w);
        *(uint4*)(out + i) = *(uint4*)h;
    }
}

// ----------------------------------------------------------------------------
// Stable argsort of mod_age + scatter bookkeeping (parallel ballot scan).
// ----------------------------------------------------------------------------
__global__ void fuse_prep_kernel(const int* __restrict__ mod_idx,
                                 const float* __restrict__ mod_age)
{
    __shared__ float a[LS];
    __shared__ int   ord[LS];
    __shared__ int   sid[LS];
    __shared__ int   wsum[32];
    int b = blockIdx.x;
    int j = threadIdx.x;
    a[j] = mod_age[b * LS + j];
    __syncthreads();
    float aj = a[j];
    int r = 0;
    #pragma unroll 4
    for (int i = 0; i < LS; i++) {
        float ai = a[i];
        r += (ai < aj) || (ai == aj && i < j);
    }
    ord[r] = j;
    __syncthreads();
    sid[j] = mod_idx[b * LS + ord[j]];
    __syncthreads();

    int lane = j & 31, wid = j >> 5;
    int m2 = (sid[j] == 2);
    unsigned bal = __ballot_sync(FULLMASK, m2);
    int excl = __popc(bal & ((1u << lane) - 1));
    if (lane == 0) wsum[wid] = __popc(bal);
    __syncthreads();
    if (j < 32) {
        int v = wsum[j];
        int s = v;
        #pragma unroll
        for (int off = 1; off < 32; off <<= 1) {
            int t = __shfl_up_sync(FULLMASK, s, off);
            if (j >= off) s += t;
        }
        wsum[j] = s - v;
    }
    __syncthreads();
    int c2 = wsum[wid] + excl;
    int c3 = j - c2;
    int src;
    if (m2) src = b * HALF + min(c2, HALF - 1);
    else    src = (b * HALF + min(c3, HALF - 1)) | (1 << 30);
    g_src[b * LS + j] = src;
}

// ----------------------------------------------------------------------------
// LayerNorm over 768-wide rows -> fp16 output. 256 threads, 3 elems each.
// ----------------------------------------------------------------------------
__device__ __forceinline__ void ln_row_body(const float* __restrict__ p,
                                            __half* __restrict__ o,
                                            const float* __restrict__ w,
                                            const float* __restrict__ bb)
{
    int t = threadIdx.x;
    float x0 = p[t], x1 = p[t + 256], x2 = p[t + 512];
    float s = x0 + x1 + x2;
    float q = x0 * x0 + x1 * x1 + x2 * x2;
    #pragma unroll
    for (int off = 16; off; off >>= 1) {
        s += __shfl_down_sync(FULLMASK, s, off);
        q += __shfl_down_sync(FULLMASK, q, off);
    }
    __shared__ float ss[8], sq[8];
    __shared__ float mr[2];
    int wid = t >> 5, lane = t & 31;
    if (lane == 0) { ss[wid] = s; sq[wid] = q; }
    __syncthreads();
    if (t == 0) {
        float S = 0.f, Q = 0.f;
        #pragma unroll
        for (int i = 0; i < 8; i++) { S += ss[i]; Q += sq[i]; }
        float mean = S * (1.f / NE);
        float var  = Q * (1.f / NE) - mean * mean;
        mr[0] = mean;
        mr[1] = rsqrtf(var + LN_EPS);
    }
    __syncthreads();
    float mean = mr[0], rstd = mr[1];
    o[t]       = __float2half_rn((x0 - mean) * rstd * w[t]       + bb[t]);
    o[t + 256] = __float2half_rn((x1 - mean) * rstd * w[t + 256] + bb[t + 256]);
    o[t + 512] = __float2half_rn((x2 - mean) * rstd * w[t + 512] + bb[t + 512]);
}

__global__ void ln_kernel(const float* __restrict__ in, __half* __restrict__ out,
                          const float* __restrict__ w, const float* __restrict__ b)
{
    int row = blockIdx.x;
    ln_row_body(in + (size_t)row * NE, out + (size_t)row * NE, w, b);
}

// Both pre-attention LayerNorms in one launch: grid.y=0 -> LN(x),
// grid.y=1 -> gathered LN of fused modality embeddings.
__global__ void ln_both_kernel(const float* __restrict__ x,
                               const float* __restrict__ mod2,
                               const float* __restrict__ mod3,
                               __half* __restrict__ xnh, __half* __restrict__ snh,
                               const float* __restrict__ ln1_w, const float* __restrict__ ln1_b,
                               const float* __restrict__ ln0_w, const float* __restrict__ ln0_b)
{
    int row = blockIdx.x;
    if (blockIdx.y == 0) {
        ln_row_body(x + (size_t)row * NE, xnh + (size_t)row * NE, ln1_w, ln1_b);
    } else {
        int s = g_src[row];
        const float* tab = (s & (1 << 30)) ? mod3 : mod2;
        const float* p = tab + (size_t)(s & 0x3FFFFFFF) * NE;
        ln_row_body(p, snh + (size_t)row * NE, ln0_w, ln0_b);
    }
}

// ----------------------------------------------------------------------------
// Shared GEMM machinery: BK=32, 64B smem rows, XOR swizzle.
// ----------------------------------------------------------------------------
#define BN 128
#define BK 32

__device__ __forceinline__ int sw_off(int r, int c) {
    return r * 64 + ((c ^ ((r >> 1) & 3)) << 4);
}

// ----------------------------------------------------------------------------
// HMMA fp16 GEMM, templated M-tile: BM = 64*MI, BN=128.
// EPI: 0 = fp32 out; 1 = fp32 out + residual; 2 = gelu -> fp16; 3 = fp16 out
// ----------------------------------------------------------------------------
template<int EPI, int MI>
__global__ void __launch_bounds__(256, 4 - MI)
hgemm_kernel(const __half* __restrict__ A, const __half* __restrict__ W,
             const float* __restrict__ bias, const float* __restrict__ res,
             void* __restrict__ Cout, int M, int N, int K)
{
    constexpr int BM = 64 * MI;
    __shared__ __align__(128) __half sA[3][BM * BK];
    __shared__ __align__(128) __half sB[3][BN * BK];

    const int tid = threadIdx.x;
    const int lane = tid & 31, wid = tid >> 5;
    const int warp_m = wid & 3, warp_n = wid >> 2;
    const int m0 = blockIdx.y * BM, n0 = blockIdx.x * BN;

    float acc[MI][8][4];
    #pragma unroll
    for (int im = 0; im < MI; im++)
        #pragma unroll
        for (int jn = 0; jn < 8; jn++)
            #pragma unroll
            for (int r = 0; r < 4; r++) acc[im][jn][r] = 0.f;

    const int ld_row = tid >> 2;
    const int ld_sub = tid & 3;
    const int nk = K / BK;

    auto load_stage = [&](int s, int kt) {
        const __half* Ag = A + (size_t)m0 * K + kt * BK;
        const __half* Bg = W + (size_t)n0 * K + kt * BK;
        #pragma unroll
        for (int i = 0; i < MI; i++) {
            int row = ld_row + i * 64;
            int off = sw_off(row, ld_sub);
            uint32_t da = smem_u32((const uint8_t*)sA[s] + off);
            const void* ga = Ag + (size_t)row * K + ld_sub * 8;
            asm volatile("cp.async.cg.shared.global [%0], [%1], 16;" :: "r"(da), "l"(ga));
        }
        #pragma unroll
        for (int i = 0; i < 2; i++) {
            int row = ld_row + i * 64;
            int off = sw_off(row, ld_sub);
            uint32_t db = smem_u32((const uint8_t*)sB[s] + off);
            const void* gb = Bg + (size_t)row * K + ld_sub * 8;
            asm volatile("cp.async.cg.shared.global [%0], [%1], 16;" :: "r"(db), "l"(gb));
        }
    };

    load_stage(0, 0);
    asm volatile("cp.async.commit_group;" ::: "memory");
    load_stage(1, 1);
    asm volatile("cp.async.commit_group;" ::: "memory");

    const int a_r0 = warp_m * (16 * MI) + (lane & 15);
    const int a_ch = lane >> 4;
    const int b_r0 = warp_n * 64 + (lane & 7) + ((lane >> 4) << 3);
    const int b_ch = (lane >> 3) & 1;

    int buf = 0;
    for (int kt = 0; kt < nk; kt++) {
        asm volatile("cp.async.wait_group 1;" ::: "memory");
        __syncthreads();
        if (kt + 2 < nk) {
            int s2 = buf + 2; if (s2 >= 3) s2 -= 3;
            load_stage(s2, kt + 2);
        }
        asm volatile("cp.async.commit_group;" ::: "memory");

        const uint32_t baseA = smem_u32(sA[buf]);
        const uint32_t baseB = smem_u32(sB[buf]);

        #pragma unroll
        for (int ks = 0; ks < 2; ks++) {
            uint32_t af[MI][4];
            #pragma unroll
            for (int im = 0; im < MI; im++) {
                int r = a_r0 + im * 16;
                uint32_t addr = baseA + sw_off(r, ks * 2 + a_ch);
                asm volatile("ldmatrix.sync.aligned.m8n8.x4.shared.b16 {%0,%1,%2,%3}, [%4];"
                             : "=r"(af[im][0]), "=r"(af[im][1]), "=r"(af[im][2]), "=r"(af[im][3])
                             : "r"(addr));
            }
            uint32_t bf[8][2];
            #pragma unroll
            for (int j4 = 0; j4 < 4; j4++) {
                uint32_t r0, r1, r2, r3;
                int r = b_r0 + j4 * 16;
                uint32_t addr = baseB + sw_off(r, ks * 2 + b_ch);
                asm volatile("ldmatrix.sync.aligned.m8n8.x4.shared.b16 {%0,%1,%2,%3}, [%4];"
                             : "=r"(r0), "=r"(r1), "=r"(r2), "=r"(r3) : "r"(addr));
                bf[2 * j4][0] = r0; bf[2 * j4][1] = r1;
                bf[2 * j4 + 1][0] = r2; bf[2 * j4 + 1][1] = r3;
            }
            #pragma unroll
            for (int im = 0; im < MI; im++)
                #pragma unroll
                for (int jn = 0; jn < 8; jn++) {
                    asm volatile(
                        "mma.sync.aligned.m16n8k16.row.col.f32.f16.f16.f32 "
                        "{%0,%1,%2,%3}, {%4,%5,%6,%7}, {%8,%9}, {%0,%1,%2,%3};"
                        : "+f"(acc[im][jn][0]), "+f"(acc[im][jn][1]),
                          "+f"(acc[im][jn][2]), "+f"(acc[im][jn][3])
                        : "r"(af[im][0]), "r"(af[im][1]), "r"(af[im][2]), "r"(af[im][3]),
                          "r"(bf[jn][0]), "r"(bf[jn][1]));
                }
        }
        buf++; if (buf == 3) buf = 0;
    }

    #pragma unroll
    for (int im = 0; im < MI; im++) {
        #pragma unroll
        for (int jn = 0; jn < 8; jn++) {
            int n = n0 + warp_n * 64 + jn * 8 + (lane & 3) * 2;
            float b0 = bias[n], b1 = bias[n + 1];
            #pragma unroll
            for (int rp = 0; rp < 2; rp++) {
                int m = m0 + warp_m * (16 * MI) + im * 16 + (lane >> 2) + 8 * rp;
                float v0 = acc[im][jn][2 * rp]     + b0;
                float v1 = acc[im][jn][2 * rp + 1] + b1;
                if (EPI == 1) {
                    const float* rr = res + (size_t)m * N + n;
                    v0 += rr[0]; v1 += rr[1];
                }
                if (EPI == 2) {
                    v0 = 0.5f * v0 * (1.f + erff(v0 * 0.70710678118654752f));
                    v1 = 0.5f * v1 * (1.f + erff(v1 * 0.70710678118654752f));
                }
                if (EPI == 2 || EPI == 3) {
                    *(__half2*)((__half*)Cout + (size_t)m * N + n) = __floats2half2_rn(v0, v1);
                } else {
                    *(float2*)((float*)Cout + (size_t)m * N + n) = make_float2(v0, v1);
                }
            }
        }
    }
}

// ----------------------------------------------------------------------------
// Fused Q/K/V GEMM: one launch over N = 3*NE = 2304.  BM=128 (MI=2), BN=128.
// Segment = n0/NE: 0 -> Q (A = xn), 1 -> K (A = sn), 2 -> V (A = sn).
// BN | NE so every CTA is segment-pure. fp16 output into g_qh/g_kh/g_vh.
// ----------------------------------------------------------------------------
__global__ void __launch_bounds__(256, 2)
qkv_gemm_kernel(const __half* __restrict__ Axn, const __half* __restrict__ Asn,
                const __half* __restrict__ Wq, const __half* __restrict__ Wk,
                const __half* __restrict__ Wv,
                const float* __restrict__ q_b, const float* __restrict__ k_b,
                const float* __restrict__ v_b,
                __half* __restrict__ Oq, __half* __restrict__ Ok, __half* __restrict__ Ov)
{
    constexpr int MI = 2;
    constexpr int BM = 128;
    constexpr int K = NE;
    __shared__ __align__(128) __half sA[3][BM * BK];
    __shared__ __align__(128) __half sB[3][BN * BK];

    const int tid = threadIdx.x;
    const int lane = tid & 31, wid = tid >> 5;
    const int warp_m = wid & 3, warp_n = wid >> 2;
    const int m0 = blockIdx.y * BM;
    const int ng0 = blockIdx.x * BN;            // global n in [0, 2304)
    const int seg = ng0 / NE;                    // 0=Q 1=K 2=V
    const int n0 = ng0 - seg * NE;               // local n within segment

    const __half* A = (seg == 0) ? Axn : Asn;
    const __half* W = (seg == 0) ? Wq : (seg == 1) ? Wk : Wv;
    const float* bias = (seg == 0) ? q_b : (seg == 1) ? k_b : v_b;
    __half* Out = (seg == 0) ? Oq : (seg == 1) ? Ok : Ov;

    float acc[MI][8][4];
    #pragma unroll
    for (int im = 0; im < MI; im++)
        #pragma unroll
        for (int jn = 0; jn < 8; jn++)
            #pragma unroll
            for (int r = 0; r < 4; r++) acc[im][jn][r] = 0.f;

    const int ld_row = tid >> 2;
    const int ld_sub = tid & 3;
    const int nk = K / BK;   // 24

    auto load_stage = [&](int s, int kt) {
        const __half* Ag = A + (size_t)m0 * K + kt * BK;
        const __half* Bg = W + (size_t)n0 * K + kt * BK;
        #pragma unroll
        for (int i = 0; i < MI; i++) {
            int row = ld_row + i * 64;
            int off = sw_off(row, ld_sub);
            uint32_t da = smem_u32((const uint8_t*)sA[s] + off);
            const void* ga = Ag + (size_t)row * K + ld_sub * 8;
            asm volatile("cp.async.cg.shared.global [%0], [%1], 16;" :: "r"(da), "l"(ga));
        }
        #pragma unroll
        for (int i = 0; i < 2; i++) {
            int row = ld_row + i * 64;
            int off = sw_off(row, ld_sub);
            uint32_t db = smem_u32((const uint8_t*)sB[s] + off);
            const void* gb = Bg + (size_t)row * K + ld_sub * 8;
            asm volatile("cp.async.cg.shared.global [%0], [%1], 16;" :: "r"(db), "l"(gb));
        }
    };

    load_stage(0, 0);
    asm volatile("cp.async.commit_group;" ::: "memory");
    load_stage(1, 1);
    asm volatile("cp.async.commit_group;" ::: "memory");

    const int a_r0 = warp_m * (16 * MI) + (lane & 15);
    const int a_ch = lane >> 4;
    const int b_r0 = warp_n * 64 + (lane & 7) + ((lane >> 4) << 3);
    const int b_ch = (lane >> 3) & 1;

    int buf = 0;
    for (int kt = 0; kt < nk; kt++) {
        asm volatile("cp.async.wait_group 1;" ::: "memory");
        __syncthreads();
        if (kt + 2 < nk) {
            int s2 = buf + 2; if (s2 >= 3) s2 -= 3;
            load_stage(s2, kt + 2);
        }
        asm volatile("cp.async.commit_group;" ::: "memory");

        const uint32_t baseA = smem_u32(sA[buf]);
        const uint32_t baseB = smem_u32(sB[buf]);

        #pragma unroll
        for (int ks = 0; ks < 2; ks++) {
            uint32_t af[MI][4];
            #pragma unroll
            for (int im = 0; im < MI; im++) {
                int r = a_r0 + im * 16;
                uint32_t addr = baseA + sw_off(r, ks * 2 + a_ch);
                asm volatile("ldmatrix.sync.aligned.m8n8.x4.shared.b16 {%0,%1,%2,%3}, [%4];"
                             : "=r"(af[im][0]), "=r"(af[im][1]), "=r"(af[im][2]), "=r"(af[im][3])
                             : "r"(addr));
            }
            uint32_t bf[8][2];
            #pragma unroll
            for (int j4 = 0; j4 < 4; j4++) {
                uint32_t r0, r1, r2, r3;
                int r = b_r0 + j4 * 16;
                uint32_t addr = baseB + sw_off(r, ks * 2 + b_ch);
                asm volatile("ldmatrix.sync.aligned.m8n8.x4.shared.b16 {%0,%1,%2,%3}, [%4];"
                             : "=r"(r0), "=r"(r1), "=r"(r2), "=r"(r3) : "r"(addr));
                bf[2 * j4][0] = r0; bf[2 * j4][1] = r1;
                bf[2 * j4 + 1][0] = r2; bf[2 * j4 + 1][1] = r3;
            }
            #pragma unroll
            for (int im = 0; im < MI; im++)
                #pragma unroll
                for (int jn = 0; jn < 8; jn++) {
                    asm volatile(
                        "mma.sync.aligned.m16n8k16.row.col.f32.f16.f16.f32 "
                        "{%0,%1,%2,%3}, {%4,%5,%6,%7}, {%8,%9}, {%0,%1,%2,%3};"
                        : "+f"(acc[im][jn][0]), "+f"(acc[im][jn][1]),
                          "+f"(acc[im][jn][2]), "+f"(acc[im][jn][3])
                        : "r"(af[im][0]), "r"(af[im][1]), "r"(af[im][2]), "r"(af[im][3]),
                          "r"(bf[jn][0]), "r"(bf[jn][1]));
                }
        }
        buf++; if (buf == 3) buf = 0;
    }

    #pragma unroll
    for (int im = 0; im < MI; im++) {
        #pragma unroll
        for (int jn = 0; jn < 8; jn++) {
            int n = n0 + warp_n * 64 + jn * 8 + (lane & 3) * 2;
            float b0 = bias[n], b1 = bias[n + 1];
            #pragma unroll
            for (int rp = 0; rp < 2; rp++) {
                int m = m0 + warp_m * (16 * MI) + im * 16 + (lane >> 2) + 8 * rp;
                float v0 = acc[im][jn][2 * rp]     + b0;
                float v1 = acc[im][jn][2 * rp + 1] + b1;
                *(__half2*)(Out + (size_t)m * NE + n) = __floats2half2_rn(v0, v1);
            }
        }
    }
}

// ----------------------------------------------------------------------------
// Tensorized flash attention (R10, validated). CTA = 64 q-rows, 4 warps.
// ----------------------------------------------------------------------------
__device__ __forceinline__ int swb(int r, int c) {
    return r * 128 + ((c ^ (r & 7)) << 4);
}

__global__ void __launch_bounds__(128)
attn_mma_kernel(const __half* __restrict__ Q, const __half* __restrict__ K,
                const __half* __restrict__ V, const float* __restrict__ age,
                const float* __restrict__ mage, __half* __restrict__ Y)
{
    const int b = blockIdx.z, h = blockIdx.y;
    const int q0 = blockIdx.x * 64;
    const int tid = threadIdx.x, wid = tid >> 5, lane = tid & 31;

    __shared__ __align__(128) __half sQ[64 * 64];
    __shared__ __align__(128) __half sK[2][64 * 64];
    __shared__ __align__(128) __half sV[2][64 * 64];
    __shared__ int s_km[64];

    #pragma unroll
    for (int i = 0; i < 4; i++) {
        int id = i * 128 + tid, r = id >> 3, c = id & 7;
        uint32_t d = smem_u32((uint8_t*)sQ + swb(r, c));
        const void* g = Q + ((size_t)(b * LM + q0 + r) * NE + h * HD + c * 8);
        asm volatile("cp.async.cg.shared.global [%0], [%1], 16;" :: "r"(d), "l"(g));
    }
    asm volatile("cp.async.commit_group;" ::: "memory");

    auto load_kv = [&](int s, int kt) {
        #pragma unroll
        for (int i = 0; i < 4; i++) {
            int id = i * 128 + tid, r = id >> 3, c = id & 7;
            size_t gofs = (size_t)(b * LS + kt + r) * NE + h * HD + c * 8;
            uint32_t dk = smem_u32((uint8_t*)sK[s] + swb(r, c));
            asm volatile("cp.async.cg.shared.global [%0], [%1], 16;" :: "r"(dk), "l"((const void*)(K + gofs)));
            uint32_t dv = smem_u32((uint8_t*)sV[s] + swb(r, c));
            asm volatile("cp.async.cg.shared.global [%0], [%1], 16;" :: "r"(dv), "l"((const void*)(V + gofs)));
        }
        asm volatile("cp.async.commit_group;" ::: "memory");
    };
    load_kv(0, 0);

    if (tid < 64) {
        float a = age[b * LM + q0 + tid];
        const float* ma = mage + b * LS;
        int lo = 0, hi = LS;
        while (lo < hi) {
            int mid = (lo + hi) >> 1;
            if (ma[mid] <= a) lo = mid + 1; else hi = mid;
        }
        s_km[tid] = lo;
    }
    __syncthreads();

    const int rq    = lane >> 2;
    const int km1   = s_km[wid * 16 + rq];
    const int km2   = s_km[wid * 16 + rq + 8];
    const int km_hi = s_km[wid * 16 + 15];
    const int nt    = (s_km[63] + 63) >> 6;

    float m1 = -INFINITY, m2 = -INFINITY, l1 = 0.f, l2 = 0.f;
    float o[8][4];
    #pragma unroll
    for (int j = 0; j < 8; j++)
        #pragma unroll
        for (int r = 0; r < 4; r++) o[j][r] = 0.f;
    uint32_t qf[4][4];

    for (int t = 0; t < nt; t++) {
        const int kt = t * 64;
        asm volatile("cp.async.wait_group 0;" ::: "memory");
        __syncthreads();
        if (t + 1 < nt) load_kv((t + 1) & 1, kt + 64);

        if (t == 0) {
            int ar = wid * 16 + (lane & 15);
            #pragma unroll
            for (int kc = 0; kc < 4; kc++) {
                uint32_t addr = smem_u32((uint8_t*)sQ + swb(ar, kc * 2 + (lane >> 4)));
                asm volatile("ldmatrix.sync.aligned.m8n8.x4.shared.b16 {%0,%1,%2,%3}, [%4];"
                             : "=r"(qf[kc][0]), "=r"(qf[kc][1]), "=r"(qf[kc][2]), "=r"(qf[kc][3])
                             : "r"(addr));
            }
        }

        if (kt < km_hi) {
            const int bufi = t & 1;
            float s[8][4];
            #pragma unroll
            for (int j = 0; j < 8; j++)
                #pragma unroll
                for (int r = 0; r < 4; r++) s[j][r] = 0.f;

            const int br = (lane & 7) + ((lane >> 4) << 3);
            const int bc = (lane >> 3) & 1;
            #pragma unroll
            for (int kc = 0; kc < 4; kc++) {
                uint32_t kf[8][2];
                #pragma unroll
                for (int j4 = 0; j4 < 4; j4++) {
                    uint32_t r0, r1, r2, r3;
                    int r = br + j4 * 16;
                    uint32_t addr = smem_u32((uint8_t*)sK[bufi] + swb(r, kc * 2 + bc));
                    asm volatile("ldmatrix.sync.aligned.m8n8.x4.shared.b16 {%0,%1,%2,%3}, [%4];"
                                 : "=r"(r0), "=r"(r1), "=r"(r2), "=r"(r3) : "r"(addr));
                    kf[2 * j4][0] = r0; kf[2 * j4][1] = r1;
                    kf[2 * j4 + 1][0] = r2; kf[2 * j4 + 1][1] = r3;
                }
                #pragma unroll
                for (int j = 0; j < 8; j++) {
                    asm volatile(
                        "mma.sync.aligned.m16n8k16.row.col.f32.f16.f16.f32 "
                        "{%0,%1,%2,%3}, {%4,%5,%6,%7}, {%8,%9}, {%0,%1,%2,%3};"
                        : "+f"(s[j][0]), "+f"(s[j][1]), "+f"(s[j][2]), "+f"(s[j][3])
                        : "r"(qf[kc][0]), "r"(qf[kc][1]), "r"(qf[kc][2]), "r"(qf[kc][3]),
                          "r"(kf[j][0]), "r"(kf[j][1]));
                }
            }

            const int colb = kt + 2 * (lane & 3);
            #pragma unroll
            for (int j = 0; j < 8; j++) {
                int c0 = colb + 8 * j;
                s[j][0] = (c0     < km1) ? s[j][0] * 0.125f : -INFINITY;
                s[j][1] = (c0 + 1 < km1) ? s[j][1] * 0.125f : -INFINITY;
                s[j][2] = (c0     < km2) ? s[j][2] * 0.125f : -INFINITY;
                s[j][3] = (c0 + 1 < km2) ? s[j][3] * 0.125f : -INFINITY;
            }

            float mt1 = -INFINITY, mt2 = -INFINITY;
            #pragma unroll
            for (int j = 0; j < 8; j++) {
                mt1 = fmaxf(mt1, fmaxf(s[j][0], s[j][1]));
                mt2 = fmaxf(mt2, fmaxf(s[j][2], s[j][3]));
            }
            mt1 = fmaxf(mt1, __shfl_xor_sync(FULLMASK, mt1, 1));
            mt1 = fmaxf(mt1, __shfl_xor_sync(FULLMASK, mt1, 2));
            mt2 = fmaxf(mt2, __shfl_xor_sync(FULLMASK, mt2, 1));
            mt2 = fmaxf(mt2, __shfl_xor_sync(FULLMASK, mt2, 2));
            float mn1 = fmaxf(m1, mt1), mn2 = fmaxf(m2, mt2);
            float ms1 = fmaxf(mn1, -1e30f), ms2 = fmaxf(mn2, -1e30f);
            float corr1 = __expf(m1 - ms1), corr2 = __expf(m2 - ms2);
            float ps1 = 0.f, ps2 = 0.f;
            #pragma unroll
            for (int j = 0; j < 8; j++) {
                s[j][0] = __expf(s[j][0] - ms1);
                s[j][1] = __expf(s[j][1] - ms1);
                s[j][2] = __expf(s[j][2] - ms2);
                s[j][3] = __expf(s[j][3] - ms2);
                ps1 += s[j][0] + s[j][1];
                ps2 += s[j][2] + s[j][3];
            }
            ps1 += __shfl_xor_sync(FULLMASK, ps1, 1);
            ps1 += __shfl_xor_sync(FULLMASK, ps1, 2);
            ps2 += __shfl_xor_sync(FULLMASK, ps2, 1);
            ps2 += __shfl_xor_sync(FULLMASK, ps2, 2);
            l1 = l1 * corr1 + ps1;
            l2 = l2 * corr2 + ps2;
            m1 = mn1; m2 = mn2;
            #pragma unroll
            for (int j = 0; j < 8; j++) {
                o[j][0] *= corr1; o[j][1] *= corr1;
                o[j][2] *= corr2; o[j][3] *= corr2;
            }

            const int vr0 = ((lane >> 3) & 1) * 8 + (lane & 7);
            #pragma unroll
            for (int kc = 0; kc < 4; kc++) {
                uint32_t pa[4];
                __half2* pah = (__half2*)pa;
                pah[0] = __floats2half2_rn(s[2 * kc][0], s[2 * kc][1]);
                pah[1] = __floats2half2_rn(s[2 * kc][2], s[2 * kc][3]);
                pah[2] = __floats2half2_rn(s[2 * kc + 1][0], s[2 * kc + 1][1]);
                pah[3] = __floats2half2_rn(s[2 * kc + 1][2], s[2 * kc + 1][3]);
                #pragma unroll
                for (int dg = 0; dg < 4; dg++) {
                    uint32_t v0, v1, v2, v3;
                    int r = kc * 16 + vr0;
                    uint32_t addr = smem_u32((uint8_t*)sV[bufi] + swb(r, dg * 2 + (lane >> 4)));
                    asm volatile("ldmatrix.sync.aligned.m8n8.x4.trans.shared.b16 {%0,%1,%2,%3}, [%4];"
                                 : "=r"(v0), "=r"(v1), "=r"(v2), "=r"(v3) : "r"(addr));
                    asm volatile(
                        "mma.sync.aligned.m16n8k16.row.col.f32.f16.f16.f32 "
                        "{%0,%1,%2,%3}, {%4,%5,%6,%7}, {%8,%9}, {%0,%1,%2,%3};"
                        : "+f"(o[2 * dg][0]), "+f"(o[2 * dg][1]), "+f"(o[2 * dg][2]), "+f"(o[2 * dg][3])
                        : "r"(pa[0]), "r"(pa[1]), "r"(pa[2]), "r"(pa[3]), "r"(v0), "r"(v1));
                    asm volatile(
                        "mma.sync.aligned.m16n8k16.row.col.f32.f16.f16.f32 "
                        "{%0,%1,%2,%3}, {%4,%5,%6,%7}, {%8,%9}, {%0,%1,%2,%3};"
                        : "+f"(o[2 * dg + 1][0]), "+f"(o[2 * dg + 1][1]), "+f"(o[2 * dg + 1][2]), "+f"(o[2 * dg + 1][3])
                        : "r"(pa[0]), "r"(pa[1]), "r"(pa[2]), "r"(pa[3]), "r"(v2), "r"(v3));
                }
            }
        }
    }

    float inv1 = (l1 > 0.f) ? (1.f / l1) : 0.f;
    float inv2 = (l2 > 0.f) ? (1.f / l2) : 0.f;
    size_t row1 = (size_t)(b * LM + q0 + wid * 16 + rq);
    #pragma unroll
    for (int j = 0; j < 8; j++) {
        int col = h * HD + 8 * j + 2 * (lane & 3);
        *(__half2*)(Y + row1 * NE + col)       = __floats2half2_rn(o[j][0] * inv1, o[j][1] * inv1);
        *(__half2*)(Y + (row1 + 8) * NE + col) = __floats2half2_rn(o[j][2] * inv2, o[j][3] * inv2);
    }
}

// ----------------------------------------------------------------------------
// Launch  (launch #3 = fused QKV GEMM = empirical ncu capture slot)
// ----------------------------------------------------------------------------
extern "C" void kernel_launch(void* const* d_in, const int* in_sizes, int n_in,
                              void* d_out, int out_size)
{
    const float* x        = (const float*)d_in[0];
    const float* age      = (const float*)d_in[1];
    const int*   mod_idx  = (const int*)  d_in[2];
    const float* mod_age  = (const float*)d_in[3];
    const float* mod2     = (const float*)d_in[4];
    const float* mod3     = (const float*)d_in[5];
    const float* ln0_w    = (const float*)d_in[6];
    const float* ln0_b    = (const float*)d_in[7];
    const float* ln1_w    = (const float*)d_in[8];
    const float* ln1_b    = (const float*)d_in[9];
    const float* ln2_w    = (const float*)d_in[10];
    const float* ln2_b    = (const float*)d_in[11];
    const float* q_w      = (const float*)d_in[12];
    const float* q_b      = (const float*)d_in[13];
    const float* k_w      = (const float*)d_in[14];
    const float* k_b      = (const float*)d_in[15];
    const float* v_w      = (const float*)d_in[16];
    const float* v_b      = (const float*)d_in[17];
    const float* c_w      = (const float*)d_in[18];
    const float* c_b      = (const float*)d_in[19];
    const float* fc_w     = (const float*)d_in[20];
    const float* fc_b     = (const float*)d_in[21];
    const float* proj_w   = (const float*)d_in[22];
    const float* proj_b   = (const float*)d_in[23];
    float* out = (float*)d_out;

    float *p_x1;
    __half *p_qh, *p_kh, *p_vh, *p_xnh, *p_snh, *p_yh, *p_hh;
    __half *p_wq, *p_wk, *p_wv, *p_wc, *p_wfc, *p_wpr;
    cudaGetSymbolAddress((void**)&p_x1,  g_x1);
    cudaGetSymbolAddress((void**)&p_qh,  g_qh);
    cudaGetSymbolAddress((void**)&p_kh,  g_kh);
    cudaGetSymbolAddress((void**)&p_vh,  g_vh);
    cudaGetSymbolAddress((void**)&p_xnh, g_xnh);
    cudaGetSymbolAddress((void**)&p_snh, g_snh);
    cudaGetSymbolAddress((void**)&p_yh,  g_yh);
    cudaGetSymbolAddress((void**)&p_hh,  g_hh);
    cudaGetSymbolAddress((void**)&p_wq,  g_wq);
    cudaGetSymbolAddress((void**)&p_wk,  g_wk);
    cudaGetSymbolAddress((void**)&p_wv,  g_wv);
    cudaGetSymbolAddress((void**)&p_wc,  g_wc);
    cudaGetSymbolAddress((void**)&p_wfc, g_wfc);
    cudaGetSymbolAddress((void**)&p_wpr, g_wpr);

    const int WSQ = NE * NE, WFC = FCD * NE;
    dim3 g64  (NE / 128, NTOK / 64);     // MI=1: c-proj, proj (384 CTAs)
    dim3 gqkv (3 * NE / 128, NTOK / 128); // fused QKV: 18 x 32 = 576 CTAs
    dim3 gfc  (FCD / 128, NTOK / 128);    // MI=2 fc: 768 CTAs
    dim3 ga   (LM / 64, NH, NB);
    dim3 gcv  (WFC / 2048, 6);
    dim3 gln  (NTOK, 2);

    fuse_prep_kernel<<<NB, LS>>>(mod_idx, mod_age);                               // 0
    ln_both_kernel<<<gln, 256>>>(x, mod2, mod3, p_xnh, p_snh,
                                 ln1_w, ln1_b, ln0_w, ln0_b);                     // 1
    f2h6_kernel<<<gcv, 256>>>(q_w, k_w, v_w, c_w, fc_w, proj_w,
                              p_wq, p_wk, p_wv, p_wc, p_wfc, p_wpr, WSQ, WFC);    // 2

    // 3: fused QKV GEMM  <-- ncu capture slot
    qkv_gemm_kernel<<<gqkv, 256>>>(p_xnh, p_snh, p_wq, p_wk, p_wv,
                                   q_b, k_b, v_b, p_qh, p_kh, p_vh);              // 3

    attn_mma_kernel<<<ga, 128>>>(p_qh, p_kh, p_vh, age, mod_age, p_yh);           // 4

    hgemm_kernel<1, 1><<<g64, 256>>>(p_yh, p_wc, c_b, x, p_x1, NTOK, NE, NE);     // 5
    ln_kernel<<<NTOK, 256>>>(p_x1, p_xnh, ln2_w, ln2_b);                          // 6
    hgemm_kernel<2, 2><<<gfc, 256>>>(p_xnh, p_wfc, fc_b, nullptr, p_hh, NTOK, FCD, NE); // 7
    hgemm_kernel<1, 1><<<g64, 256>>>(p_hh, p_wpr, proj_b, p_x1, out, NTOK, NE, FCD);    // 8
}

// round 14
// speedup vs baseline: 1.4529x; 1.4529x over previous
#include <cuda_runtime.h>
#include <cuda_fp16.h>
#include <math.h>
#include <stdint.h>

// ----------------------------------------------------------------------------
// Problem constants
// ----------------------------------------------------------------------------
#define NB 4
#define LM 1024
#define LS 1024
#define NE 768
#define NH 12
#define HD 64
#define HALF 512
#define NTOK (NB * LM)          // 4096
#define FCD (4 * NE)            // 3072
#define LN_EPS 1e-5f
#define FULLMASK 0xffffffffu

// ----------------------------------------------------------------------------
// Scratch (device globals -- no runtime allocation allowed)
// ----------------------------------------------------------------------------
__device__ float  g_x1[NTOK * NE];
__device__ __half g_qh [NTOK * NE];
__device__ __half g_kh [NTOK * NE];
__device__ __half g_vh [NTOK * NE];
__device__ __half g_xnh[NTOK * NE];
__device__ __half g_snh[NTOK * NE];
__device__ __half g_yh [NTOK * NE];
__device__ __half g_hh [NTOK * FCD];
__device__ __half g_wq [NE * NE];
__device__ __half g_wk [NE * NE];
__device__ __half g_wv [NE * NE];
__device__ __half g_wc [NE * NE];
__device__ __half g_wfc[FCD * NE];
__device__ __half g_wpr[NE * FCD];
__device__ int g_src[NB * LS];

__device__ __forceinline__ uint32_t smem_u32(const void* p) {
    return (uint32_t)__cvta_generic_to_shared(p);
}

// ----------------------------------------------------------------------------
// Batched fp32 -> fp16 conversion: 6 segments in one launch.
// ----------------------------------------------------------------------------
__global__ void f2h6_kernel(const float* __restrict__ s0, const float* __restrict__ s1,
                            const float* __restrict__ s2, const float* __restrict__ s3,
                            const float* __restrict__ s4, const float* __restrict__ s5,
                            __half* __restrict__ d0, __half* __restrict__ d1,
                            __half* __restrict__ d2, __half* __restrict__ d3,
                            __half* __restrict__ d4, __half* __restrict__ d5,
                            int n_sq, int n_fc)
{
    const float* in; __half* out; int n;
    switch (blockIdx.y) {
        case 0: in = s0; out = d0; n = n_sq; break;
        case 1: in = s1; out = d1; n = n_sq; break;
        case 2: in = s2; out = d2; n = n_sq; break;
        case 3: in = s3; out = d3; n = n_sq; break;
        case 4: in = s4; out = d4; n = n_fc; break;
        default: in = s5; out = d5; n = n_fc; break;
    }
    int i = (blockIdx.x * 256 + threadIdx.x) * 8;
    if (i < n) {
        float4 a = *(const float4*)(in + i);
        float4 b = *(const float4*)(in + i + 4);
        __half2 h[4];
        h[0] = __floats2half2_rn(a.x, a.y);
        h[1] = __floats2half2_rn(a.z, a.w);
        h[2] = __floats2half2_rn(b.x, b.y);
        h[3] = __floats2half2_rn(b.z, b.w);
        *(uint4*)(out + i) = *(uint4*)h;
    }
}

// ----------------------------------------------------------------------------
// Stable argsort of mod_age + scatter bookkeeping (parallel ballot scan).
// ----------------------------------------------------------------------------
__global__ void fuse_prep_kernel(const int* __restrict__ mod_idx,
                                 const float* __restrict__ mod_age)
{
    __shared__ float a[LS];
    __shared__ int   ord[LS];
    __shared__ int   sid[LS];
    __shared__ int   wsum[32];
    int b = blockIdx.x;
    int j = threadIdx.x;
    a[j] = mod_age[b * LS + j];
    __syncthreads();
    float aj = a[j];
    int r = 0;
    #pragma unroll 4
    for (int i = 0; i < LS; i++) {
        float ai = a[i];
        r += (ai < aj) || (ai == aj && i < j);
    }
    ord[r] = j;
    __syncthreads();
    sid[j] = mod_idx[b * LS + ord[j]];
    __syncthreads();

    int lane = j & 31, wid = j >> 5;
    int m2 = (sid[j] == 2);
    unsigned bal = __ballot_sync(FULLMASK, m2);
    int excl = __popc(bal & ((1u << lane) - 1));
    if (lane == 0) wsum[wid] = __popc(bal);
    __syncthreads();
    if (j < 32) {
        int v = wsum[j];
        int s = v;
        #pragma unroll
        for (int off = 1; off < 32; off <<= 1) {
            int t = __shfl_up_sync(FULLMASK, s, off);
            if (j >= off) s += t;
        }
        wsum[j] = s - v;
    }
    __syncthreads();
    int c2 = wsum[wid] + excl;
    int c3 = j - c2;
    int src;
    if (m2) src = b * HALF + min(c2, HALF - 1);
    else    src = (b * HALF + min(c3, HALF - 1)) | (1 << 30);
    g_src[b * LS + j] = src;
}

// ----------------------------------------------------------------------------
// LayerNorm over 768-wide rows -> fp16 output. 256 threads, 3 elems each.
// ----------------------------------------------------------------------------
__device__ __forceinline__ void ln_row_body(const float* __restrict__ p,
                                            __half* __restrict__ o,
                                            const float* __restrict__ w,
                                            const float* __restrict__ bb)
{
    int t = threadIdx.x;
    float x0 = p[t], x1 = p[t + 256], x2 = p[t + 512];
    float s = x0 + x1 + x2;
    float q = x0 * x0 + x1 * x1 + x2 * x2;
    #pragma unroll
    for (int off = 16; off; off >>= 1) {
        s += __shfl_down_sync(FULLMASK, s, off);
        q += __shfl_down_sync(FULLMASK, q, off);
    }
    __shared__ float ss[8], sq[8];
    __shared__ float mr[2];
    int wid = t >> 5, lane = t & 31;
    if (lane == 0) { ss[wid] = s; sq[wid] = q; }
    __syncthreads();
    if (t == 0) {
        float S = 0.f, Q = 0.f;
        #pragma unroll
        for (int i = 0; i < 8; i++) { S += ss[i]; Q += sq[i]; }
        float mean = S * (1.f / NE);
        float var  = Q * (1.f / NE) - mean * mean;
        mr[0] = mean;
        mr[1] = rsqrtf(var + LN_EPS);
    }
    __syncthreads();
    float mean = mr[0], rstd = mr[1];
    o[t]       = __float2half_rn((x0 - mean) * rstd * w[t]       + bb[t]);
    o[t + 256] = __float2half_rn((x1 - mean) * rstd * w[t + 256] + bb[t + 256]);
    o[t + 512] = __float2half_rn((x2 - mean) * rstd * w[t + 512] + bb[t + 512]);
}

__global__ void ln_kernel(const float* __restrict__ in, __half* __restrict__ out,
                          const float* __restrict__ w, const float* __restrict__ b)
{
    int row = blockIdx.x;
    ln_row_body(in + (size_t)row * NE, out + (size_t)row * NE, w, b);
}

// Both pre-attention LayerNorms in one launch: grid.y=0 -> LN(x),
// grid.y=1 -> gathered LN of fused modality embeddings.
__global__ void ln_both_kernel(const float* __restrict__ x,
                               const float* __restrict__ mod2,
                               const float* __restrict__ mod3,
                               __half* __restrict__ xnh, __half* __restrict__ snh,
                               const float* __restrict__ ln1_w, const float* __restrict__ ln1_b,
                               const float* __restrict__ ln0_w, const float* __restrict__ ln0_b)
{
    int row = blockIdx.x;
    if (blockIdx.y == 0) {
        ln_row_body(x + (size_t)row * NE, xnh + (size_t)row * NE, ln1_w, ln1_b);
    } else {
        int s = g_src[row];
        const float* tab = (s & (1 << 30)) ? mod3 : mod2;
        const float* p = tab + (size_t)(s & 0x3FFFFFFF) * NE;
        ln_row_body(p, snh + (size_t)row * NE, ln0_w, ln0_b);
    }
}

// ----------------------------------------------------------------------------
// HMMA fp16 GEMM, templated M-tile: BM = 64*MI, BN=128, BK=32 (R12-validated).
// EPI: 0 = fp32 out; 1 = fp32 out + residual; 2 = gelu -> fp16; 3 = fp16 out
// ----------------------------------------------------------------------------
#define BN 128
#define BK 32

__device__ __forceinline__ int sw_off(int r, int c) {
    return r * 64 + ((c ^ ((r >> 1) & 3)) << 4);
}

template<int EPI, int MI>
__global__ void __launch_bounds__(256, 4 - MI)
hgemm_kernel(const __half* __restrict__ A, const __half* __restrict__ W,
             const float* __restrict__ bias, const float* __restrict__ res,
             void* __restrict__ Cout, int M, int N, int K)
{
    constexpr int BM = 64 * MI;
    __shared__ __align__(128) __half sA[3][BM * BK];
    __shared__ __align__(128) __half sB[3][BN * BK];

    const int tid = threadIdx.x;
    const int lane = tid & 31, wid = tid >> 5;
    const int warp_m = wid & 3, warp_n = wid >> 2;
    const int m0 = blockIdx.y * BM, n0 = blockIdx.x * BN;

    float acc[MI][8][4];
    #pragma unroll
    for (int im = 0; im < MI; im++)
        #pragma unroll
        for (int jn = 0; jn < 8; jn++)
            #pragma unroll
            for (int r = 0; r < 4; r++) acc[im][jn][r] = 0.f;

    const int ld_row = tid >> 2;
    const int ld_sub = tid & 3;
    const int nk = K / BK;

    auto load_stage = [&](int s, int kt) {
        const __half* Ag = A + (size_t)m0 * K + kt * BK;
        const __half* Bg = W + (size_t)n0 * K + kt * BK;
        #pragma unroll
        for (int i = 0; i < MI; i++) {
            int row = ld_row + i * 64;
            int off = sw_off(row, ld_sub);
            uint32_t da = smem_u32((const uint8_t*)sA[s] + off);
            const void* ga = Ag + (size_t)row * K + ld_sub * 8;
            asm volatile("cp.async.cg.shared.global [%0], [%1], 16;" :: "r"(da), "l"(ga));
        }
        #pragma unroll
        for (int i = 0; i < 2; i++) {
            int row = ld_row + i * 64;
            int off = sw_off(row, ld_sub);
            uint32_t db = smem_u32((const uint8_t*)sB[s] + off);
            const void* gb = Bg + (size_t)row * K + ld_sub * 8;
            asm volatile("cp.async.cg.shared.global [%0], [%1], 16;" :: "r"(db), "l"(gb));
        }
    };

    load_stage(0, 0);
    asm volatile("cp.async.commit_group;" ::: "memory");
    load_stage(1, 1);
    asm volatile("cp.async.commit_group;" ::: "memory");

    const int a_r0 = warp_m * (16 * MI) + (lane & 15);
    const int a_ch = lane >> 4;
    const int b_r0 = warp_n * 64 + (lane & 7) + ((lane >> 4) << 3);
    const int b_ch = (lane >> 3) & 1;

    int buf = 0;
    for (int kt = 0; kt < nk; kt++) {
        asm volatile("cp.async.wait_group 1;" ::: "memory");
        __syncthreads();
        if (kt + 2 < nk) {
            int s2 = buf + 2; if (s2 >= 3) s2 -= 3;
            load_stage(s2, kt + 2);
        }
        asm volatile("cp.async.commit_group;" ::: "memory");

        const uint32_t baseA = smem_u32(sA[buf]);
        const uint32_t baseB = smem_u32(sB[buf]);

        #pragma unroll
        for (int ks = 0; ks < 2; ks++) {
            uint32_t af[MI][4];
            #pragma unroll
            for (int im = 0; im < MI; im++) {
                int r = a_r0 + im * 16;
                uint32_t addr = baseA + sw_off(r, ks * 2 + a_ch);
                asm volatile("ldmatrix.sync.aligned.m8n8.x4.shared.b16 {%0,%1,%2,%3}, [%4];"
                             : "=r"(af[im][0]), "=r"(af[im][1]), "=r"(af[im][2]), "=r"(af[im][3])
                             : "r"(addr));
            }
            uint32_t bf[8][2];
            #pragma unroll
            for (int j4 = 0; j4 < 4; j4++) {
                uint32_t r0, r1, r2, r3;
                int r = b_r0 + j4 * 16;
                uint32_t addr = baseB + sw_off(r, ks * 2 + b_ch);
                asm volatile("ldmatrix.sync.aligned.m8n8.x4.shared.b16 {%0,%1,%2,%3}, [%4];"
                             : "=r"(r0), "=r"(r1), "=r"(r2), "=r"(r3) : "r"(addr));
                bf[2 * j4][0] = r0; bf[2 * j4][1] = r1;
                bf[2 * j4 + 1][0] = r2; bf[2 * j4 + 1][1] = r3;
            }
            #pragma unroll
            for (int im = 0; im < MI; im++)
                #pragma unroll
                for (int jn = 0; jn < 8; jn++) {
                    asm volatile(
                        "mma.sync.aligned.m16n8k16.row.col.f32.f16.f16.f32 "
                        "{%0,%1,%2,%3}, {%4,%5,%6,%7}, {%8,%9}, {%0,%1,%2,%3};"
                        : "+f"(acc[im][jn][0]), "+f"(acc[im][jn][1]),
                          "+f"(acc[im][jn][2]), "+f"(acc[im][jn][3])
                        : "r"(af[im][0]), "r"(af[im][1]), "r"(af[im][2]), "r"(af[im][3]),
                          "r"(bf[jn][0]), "r"(bf[jn][1]));
                }
        }
        buf++; if (buf == 3) buf = 0;
    }

    #pragma unroll
    for (int im = 0; im < MI; im++) {
        #pragma unroll
        for (int jn = 0; jn < 8; jn++) {
            int n = n0 + warp_n * 64 + jn * 8 + (lane & 3) * 2;
            float b0 = bias[n], b1 = bias[n + 1];
            #pragma unroll
            for (int rp = 0; rp < 2; rp++) {
                int m = m0 + warp_m * (16 * MI) + im * 16 + (lane >> 2) + 8 * rp;
                float v0 = acc[im][jn][2 * rp]     + b0;
                float v1 = acc[im][jn][2 * rp + 1] + b1;
                if (EPI == 1) {
                    const float* rr = res + (size_t)m * N + n;
                    v0 += rr[0]; v1 += rr[1];
                }
                if (EPI == 2) {
                    v0 = 0.5f * v0 * (1.f + erff(v0 * 0.70710678118654752f));
                    v1 = 0.5f * v1 * (1.f + erff(v1 * 0.70710678118654752f));
                }
                if (EPI == 2 || EPI == 3) {
                    *(__half2*)((__half*)Cout + (size_t)m * N + n) = __floats2half2_rn(v0, v1);
                } else {
                    *(float2*)((float*)Cout + (size_t)m * N + n) = make_float2(v0, v1);
                }
            }
        }
    }
}

// ----------------------------------------------------------------------------
// Tensorized flash attention (R10, validated). CTA = 64 q-rows, 4 warps.
// ----------------------------------------------------------------------------
__device__ __forceinline__ int swb(int r, int c) {
    return r * 128 + ((c ^ (r & 7)) << 4);
}

__global__ void __launch_bounds__(128)
attn_mma_kernel(const __half* __restrict__ Q, const __half* __restrict__ K,
                const __half* __restrict__ V, const float* __restrict__ age,
                const float* __restrict__ mage, __half* __restrict__ Y)
{
    const int b = blockIdx.z, h = blockIdx.y;
    const int q0 = blockIdx.x * 64;
    const int tid = threadIdx.x, wid = tid >> 5, lane = tid & 31;

    __shared__ __align__(128) __half sQ[64 * 64];
    __shared__ __align__(128) __half sK[2][64 * 64];
    __shared__ __align__(128) __half sV[2][64 * 64];
    __shared__ int s_km[64];

    #pragma unroll
    for (int i = 0; i < 4; i++) {
        int id = i * 128 + tid, r = id >> 3, c = id & 7;
        uint32_t d = smem_u32((uint8_t*)sQ + swb(r, c));
        const void* g = Q + ((size_t)(b * LM + q0 + r) * NE + h * HD + c * 8);
        asm volatile("cp.async.cg.shared.global [%0], [%1], 16;" :: "r"(d), "l"(g));
    }
    asm volatile("cp.async.commit_group;" ::: "memory");

    auto load_kv = [&](int s, int kt) {
        #pragma unroll
        for (int i = 0; i < 4; i++) {
            int id = i * 128 + tid, r = id >> 3, c = id & 7;
            size_t gofs = (size_t)(b * LS + kt + r) * NE + h * HD + c * 8;
            uint32_t dk = smem_u32((uint8_t*)sK[s] + swb(r, c));
            asm volatile("cp.async.cg.shared.global [%0], [%1], 16;" :: "r"(dk), "l"((const void*)(K + gofs)));
            uint32_t dv = smem_u32((uint8_t*)sV[s] + swb(r, c));
            asm volatile("cp.async.cg.shared.global [%0], [%1], 16;" :: "r"(dv), "l"((const void*)(V + gofs)));
        }
        asm volatile("cp.async.commit_group;" ::: "memory");
    };
    load_kv(0, 0);

    if (tid < 64) {
        float a = age[b * LM + q0 + tid];
        const float* ma = mage + b * LS;
        int lo = 0, hi = LS;
        while (lo < hi) {
            int mid = (lo + hi) >> 1;
            if (ma[mid] <= a) lo = mid + 1; else hi = mid;
        }
        s_km[tid] = lo;
    }
    __syncthreads();

    const int rq    = lane >> 2;
    const int km1   = s_km[wid * 16 + rq];
    const int km2   = s_km[wid * 16 + rq + 8];
    const int km_hi = s_km[wid * 16 + 15];
    const int nt    = (s_km[63] + 63) >> 6;

    float m1 = -INFINITY, m2 = -INFINITY, l1 = 0.f, l2 = 0.f;
    float o[8][4];
    #pragma unroll
    for (int j = 0; j < 8; j++)
        #pragma unroll
        for (int r = 0; r < 4; r++) o[j][r] = 0.f;
    uint32_t qf[4][4];

    for (int t = 0; t < nt; t++) {
        const int kt = t * 64;
        asm volatile("cp.async.wait_group 0;" ::: "memory");
        __syncthreads();
        if (t + 1 < nt) load_kv((t + 1) & 1, kt + 64);

        if (t == 0) {
            int ar = wid * 16 + (lane & 15);
            #pragma unroll
            for (int kc = 0; kc < 4; kc++) {
                uint32_t addr = smem_u32((uint8_t*)sQ + swb(ar, kc * 2 + (lane >> 4)));
                asm volatile("ldmatrix.sync.aligned.m8n8.x4.shared.b16 {%0,%1,%2,%3}, [%4];"
                             : "=r"(qf[kc][0]), "=r"(qf[kc][1]), "=r"(qf[kc][2]), "=r"(qf[kc][3])
                             : "r"(addr));
            }
        }

        if (kt < km_hi) {
            const int bufi = t & 1;
            float s[8][4];
            #pragma unroll
            for (int j = 0; j < 8; j++)
                #pragma unroll
                for (int r = 0; r < 4; r++) s[j][r] = 0.f;

            const int br = (lane & 7) + ((lane >> 4) << 3);
            const int bc = (lane >> 3) & 1;
            #pragma unroll
            for (int kc = 0; kc < 4; kc++) {
                uint32_t kf[8][2];
                #pragma unroll
                for (int j4 = 0; j4 < 4; j4++) {
                    uint32_t r0, r1, r2, r3;
                    int r = br + j4 * 16;
                    uint32_t addr = smem_u32((uint8_t*)sK[bufi] + swb(r, kc * 2 + bc));
                    asm volatile("ldmatrix.sync.aligned.m8n8.x4.shared.b16 {%0,%1,%2,%3}, [%4];"
                                 : "=r"(r0), "=r"(r1), "=r"(r2), "=r"(r3) : "r"(addr));
                    kf[2 * j4][0] = r0; kf[2 * j4][1] = r1;
                    kf[2 * j4 + 1][0] = r2; kf[2 * j4 + 1][1] = r3;
                }
                #pragma unroll
                for (int j = 0; j < 8; j++) {
                    asm volatile(
                        "mma.sync.aligned.m16n8k16.row.col.f32.f16.f16.f32 "
                        "{%0,%1,%2,%3}, {%4,%5,%6,%7}, {%8,%9}, {%0,%1,%2,%3};"
                        : "+f"(s[j][0]), "+f"(s[j][1]), "+f"(s[j][2]), "+f"(s[j][3])
                        : "r"(qf[kc][0]), "r"(qf[kc][1]), "r"(qf[kc][2]), "r"(qf[kc][3]),
                          "r"(kf[j][0]), "r"(kf[j][1]));
                }
            }

            const int colb = kt + 2 * (lane & 3);
            #pragma unroll
            for (int j = 0; j < 8; j++) {
                int c0 = colb + 8 * j;
                s[j][0] = (c0     < km1) ? s[j][0] * 0.125f : -INFINITY;
                s[j][1] = (c0 + 1 < km1) ? s[j][1] * 0.125f : -INFINITY;
                s[j][2] = (c0     < km2) ? s[j][2] * 0.125f : -INFINITY;
                s[j][3] = (c0 + 1 < km2) ? s[j][3] * 0.125f : -INFINITY;
            }

            float mt1 = -INFINITY, mt2 = -INFINITY;
            #pragma unroll
            for (int j = 0; j < 8; j++) {
                mt1 = fmaxf(mt1, fmaxf(s[j][0], s[j][1]));
                mt2 = fmaxf(mt2, fmaxf(s[j][2], s[j][3]));
            }
            mt1 = fmaxf(mt1, __shfl_xor_sync(FULLMASK, mt1, 1));
            mt1 = fmaxf(mt1, __shfl_xor_sync(FULLMASK, mt1, 2));
            mt2 = fmaxf(mt2, __shfl_xor_sync(FULLMASK, mt2, 1));
            mt2 = fmaxf(mt2, __shfl_xor_sync(FULLMASK, mt2, 2));
            float mn1 = fmaxf(m1, mt1), mn2 = fmaxf(m2, mt2);
            float ms1 = fmaxf(mn1, -1e30f), ms2 = fmaxf(mn2, -1e30f);
            float corr1 = __expf(m1 - ms1), corr2 = __expf(m2 - ms2);
            float ps1 = 0.f, ps2 = 0.f;
            #pragma unroll
            for (int j = 0; j < 8; j++) {
                s[j][0] = __expf(s[j][0] - ms1);
                s[j][1] = __expf(s[j][1] - ms1);
                s[j][2] = __expf(s[j][2] - ms2);
                s[j][3] = __expf(s[j][3] - ms2);
                ps1 += s[j][0] + s[j][1];
                ps2 += s[j][2] + s[j][3];
            }
            ps1 += __shfl_xor_sync(FULLMASK, ps1, 1);
            ps1 += __shfl_xor_sync(FULLMASK, ps1, 2);
            ps2 += __shfl_xor_sync(FULLMASK, ps2, 1);
            ps2 += __shfl_xor_sync(FULLMASK, ps2, 2);
            l1 = l1 * corr1 + ps1;
            l2 = l2 * corr2 + ps2;
            m1 = mn1; m2 = mn2;
            #pragma unroll
            for (int j = 0; j < 8; j++) {
                o[j][0] *= corr1; o[j][1] *= corr1;
                o[j][2] *= corr2; o[j][3] *= corr2;
            }

            const int vr0 = ((lane >> 3) & 1) * 8 + (lane & 7);
            #pragma unroll
            for (int kc = 0; kc < 4; kc++) {
                uint32_t pa[4];
                __half2* pah = (__half2*)pa;
                pah[0] = __floats2half2_rn(s[2 * kc][0], s[2 * kc][1]);
                pah[1] = __floats2half2_rn(s[2 * kc][2], s[2 * kc][3]);
                pah[2] = __floats2half2_rn(s[2 * kc + 1][0], s[2 * kc + 1][1]);
                pah[3] = __floats2half2_rn(s[2 * kc + 1][2], s[2 * kc + 1][3]);
                #pragma unroll
                for (int dg = 0; dg < 4; dg++) {
                    uint32_t v0, v1, v2, v3;
                    int r = kc * 16 + vr0;
                    uint32_t addr = smem_u32((uint8_t*)sV[bufi] + swb(r, dg * 2 + (lane >> 4)));
                    asm volatile("ldmatrix.sync.aligned.m8n8.x4.trans.shared.b16 {%0,%1,%2,%3}, [%4];"
                                 : "=r"(v0), "=r"(v1), "=r"(v2), "=r"(v3) : "r"(addr));
                    asm volatile(
                        "mma.sync.aligned.m16n8k16.row.col.f32.f16.f16.f32 "
                        "{%0,%1,%2,%3}, {%4,%5,%6,%7}, {%8,%9}, {%0,%1,%2,%3};"
                        : "+f"(o[2 * dg][0]), "+f"(o[2 * dg][1]), "+f"(o[2 * dg][2]), "+f"(o[2 * dg][3])
                        : "r"(pa[0]), "r"(pa[1]), "r"(pa[2]), "r"(pa[3]), "r"(v0), "r"(v1));
                    asm volatile(
                        "mma.sync.aligned.m16n8k16.row.col.f32.f16.f16.f32 "
                        "{%0,%1,%2,%3}, {%4,%5,%6,%7}, {%8,%9}, {%0,%1,%2,%3};"
                        : "+f"(o[2 * dg + 1][0]), "+f"(o[2 * dg + 1][1]), "+f"(o[2 * dg + 1][2]), "+f"(o[2 * dg + 1][3])
                        : "r"(pa[0]), "r"(pa[1]), "r"(pa[2]), "r"(pa[3]), "r"(v2), "r"(v3));
                }
            }
        }
    }

    float inv1 = (l1 > 0.f) ? (1.f / l1) : 0.f;
    float inv2 = (l2 > 0.f) ? (1.f / l2) : 0.f;
    size_t row1 = (size_t)(b * LM + q0 + wid * 16 + rq);
    #pragma unroll
    for (int j = 0; j < 8; j++) {
        int col = h * HD + 8 * j + 2 * (lane & 3);
        *(__half2*)(Y + row1 * NE + col)       = __floats2half2_rn(o[j][0] * inv1, o[j][1] * inv1);
        *(__half2*)(Y + (row1 + 8) * NE + col) = __floats2half2_rn(o[j][2] * inv2, o[j][3] * inv2);
    }
}

// ----------------------------------------------------------------------------
// Launch  (R12 structure; launch #3 = Q hgemm = ncu capture slot)
// ----------------------------------------------------------------------------
extern "C" void kernel_launch(void* const* d_in, const int* in_sizes, int n_in,
                              void* d_out, int out_size)
{
    const float* x        = (const float*)d_in[0];
    const float* age      = (const float*)d_in[1];
    const int*   mod_idx  = (const int*)  d_in[2];
    const float* mod_age  = (const float*)d_in[3];
    const float* mod2     = (const float*)d_in[4];
    const float* mod3     = (const float*)d_in[5];
    const float* ln0_w    = (const float*)d_in[6];
    const float* ln0_b    = (const float*)d_in[7];
    const float* ln1_w    = (const float*)d_in[8];
    const float* ln1_b    = (const float*)d_in[9];
    const float* ln2_w    = (const float*)d_in[10];
    const float* ln2_b    = (const float*)d_in[11];
    const float* q_w      = (const float*)d_in[12];
    const float* q_b      = (const float*)d_in[13];
    const float* k_w      = (const float*)d_in[14];
    const float* k_b      = (const float*)d_in[15];
    const float* v_w      = (const float*)d_in[16];
    const float* v_b      = (const float*)d_in[17];
    const float* c_w      = (const float*)d_in[18];
    const float* c_b      = (const float*)d_in[19];
    const float* fc_w     = (const float*)d_in[20];
    const float* fc_b     = (const float*)d_in[21];
    const float* proj_w   = (const float*)d_in[22];
    const float* proj_b   = (const float*)d_in[23];
    float* out = (float*)d_out;

    float *p_x1;
    __half *p_qh, *p_kh, *p_vh, *p_xnh, *p_snh, *p_yh, *p_hh;
    __half *p_wq, *p_wk, *p_wv, *p_wc, *p_wfc, *p_wpr;
    cudaGetSymbolAddress((void**)&p_x1,  g_x1);
    cudaGetSymbolAddress((void**)&p_qh,  g_qh);
    cudaGetSymbolAddress((void**)&p_kh,  g_kh);
    cudaGetSymbolAddress((void**)&p_vh,  g_vh);
    cudaGetSymbolAddress((void**)&p_xnh, g_xnh);
    cudaGetSymbolAddress((void**)&p_snh, g_snh);
    cudaGetSymbolAddress((void**)&p_yh,  g_yh);
    cudaGetSymbolAddress((void**)&p_hh,  g_hh);
    cudaGetSymbolAddress((void**)&p_wq,  g_wq);
    cudaGetSymbolAddress((void**)&p_wk,  g_wk);
    cudaGetSymbolAddress((void**)&p_wv,  g_wv);
    cudaGetSymbolAddress((void**)&p_wc,  g_wc);
    cudaGetSymbolAddress((void**)&p_wfc, g_wfc);
    cudaGetSymbolAddress((void**)&p_wpr, g_wpr);

    const int WSQ = NE * NE, WFC = FCD * NE;
    dim3 g64 (NE / 128, NTOK / 64);    // MI=1 GEMMs: 384 CTAs
    dim3 gfc (FCD / 128, NTOK / 128);  // MI=2 fc GEMM: 768 CTAs
    dim3 ga  (LM / 64, NH, NB);
    dim3 gcv (WFC / 2048, 6);
    dim3 gln (NTOK, 2);

    fuse_prep_kernel<<<NB, LS>>>(mod_idx, mod_age);                               // 0
    ln_both_kernel<<<gln, 256>>>(x, mod2, mod3, p_xnh, p_snh,
                                 ln1_w, ln1_b, ln0_w, ln0_b);                     // 1
    f2h6_kernel<<<gcv, 256>>>(q_w, k_w, v_w, c_w, fc_w, proj_w,
                              p_wq, p_wk, p_wv, p_wc, p_wfc, p_wpr, WSQ, WFC);    // 2

    // 3: Q GEMM (MI=1)  <-- ncu capture slot (verify revert matches R12 profile)
    hgemm_kernel<3, 1><<<g64, 256>>>(p_xnh, p_wq, q_b, nullptr, p_qh, NTOK, NE, NE); // 3

    hgemm_kernel<3, 1><<<g64, 256>>>(p_snh, p_wk, k_b, nullptr, p_kh, NTOK, NE, NE); // 4
    hgemm_kernel<3, 1><<<g64, 256>>>(p_snh, p_wv, v_b, nullptr, p_vh, NTOK, NE, NE); // 5

    attn_mma_kernel<<<ga, 128>>>(p_qh, p_kh, p_vh, age, mod_age, p_yh);           // 6

    hgemm_kernel<1, 1><<<g64, 256>>>(p_yh, p_wc, c_b, x, p_x1, NTOK, NE, NE);     // 7
    ln_kernel<<<NTOK, 256>>>(p_x1, p_xnh, ln2_w, ln2_b);                          // 8
    hgemm_kernel<2, 2><<<gfc, 256>>>(p_xnh, p_wfc, fc_b, nullptr, p_hh, NTOK, FCD, NE); // 9
    hgemm_kernel<1, 1><<<g64, 256>>>(p_hh, p_wpr, proj_b, p_x1, out, NTOK, NE, FCD);    // 10
}